// round 7
// baseline (speedup 1.0000x reference)
#include <cuda_runtime.h>
#include <cstdint>

#define NUM_NEURONS 8192
#define INPUT_SIZE  8192
#define BATCH       2048

#define THREADS 512
#define NPT     16                 // neurons per thread (4 groups of 4)
#define GRID    148                // persistent: 1 block per SM
#define PAIRS   (BATCH / 2)        // 1024 row-pairs
#define PAIR_BYTES (2 * INPUT_SIZE * 4)   // 64 KB
#define NBUF    3

// Per-neuron collapsed coefficients: out = A + B*a1 + C*a2 + D*a1*a2
__device__ float4 g_coeff[NUM_NEURONS];

// ---------------------------------------------------------------------------
// PTX helpers (mbarrier + 1D TMA bulk copy)
// ---------------------------------------------------------------------------
__device__ __forceinline__ uint32_t smem_u32(const void* p) {
    uint32_t a;
    asm("{ .reg .u64 t; cvta.to.shared.u64 t, %1; cvt.u32.u64 %0, t; }"
        : "=r"(a) : "l"(p));
    return a;
}
__device__ __forceinline__ void mbar_init(uint32_t m, uint32_t cnt) {
    asm volatile("mbarrier.init.shared.b64 [%0], %1;" :: "r"(m), "r"(cnt) : "memory");
}
__device__ __forceinline__ void mbar_expect_tx(uint32_t m, uint32_t bytes) {
    asm volatile("mbarrier.arrive.expect_tx.shared.b64 _, [%0], %1;"
                 :: "r"(m), "r"(bytes) : "memory");
}
__device__ __forceinline__ void mbar_wait(uint32_t m, uint32_t phase) {
    asm volatile(
        "{\n\t.reg .pred P;\n\t"
        "WL_%=:\n\t"
        "mbarrier.try_wait.parity.acquire.cta.shared::cta.b64 P, [%0], %1, 0x989680;\n\t"
        "@P bra WD_%=;\n\t"
        "bra WL_%=;\n\t"
        "WD_%=:\n\t}"
        :: "r"(m), "r"(phase) : "memory");
}
__device__ __forceinline__ void tma_bulk_g2s(uint32_t dst_smem, const void* src,
                                             uint32_t bytes, uint32_t mbar) {
    asm volatile(
        "cp.async.bulk.shared::cluster.global.mbarrier::complete_tx::bytes "
        "[%0], [%1], %2, [%3];"
        :: "r"(dst_smem), "l"(src), "r"(bytes), "r"(mbar) : "memory");
}

// ---------------------------------------------------------------------------
// Precompute: softmax(w[n,:16]) dotted with the constant coefficient vectors
// of the 16 affine-in-(1,a1,a2,a1*a2) logic ops.
// ---------------------------------------------------------------------------
__global__ void coeff_kernel(const float* __restrict__ w) {
    int n = blockIdx.x * blockDim.x + threadIdx.x;
    if (n >= NUM_NEURONS) return;

    const float4* wr = reinterpret_cast<const float4*>(w) + n * 4;
    float v[16];
    float4 t;
    t = wr[0]; v[0]=t.x;  v[1]=t.y;  v[2]=t.z;  v[3]=t.w;
    t = wr[1]; v[4]=t.x;  v[5]=t.y;  v[6]=t.z;  v[7]=t.w;
    t = wr[2]; v[8]=t.x;  v[9]=t.y;  v[10]=t.z; v[11]=t.w;
    t = wr[3]; v[12]=t.x; v[13]=t.y; v[14]=t.z; v[15]=t.w;

    float m = v[0];
#pragma unroll
    for (int i = 1; i < 16; i++) m = fmaxf(m, v[i]);
    float s = 0.0f;
#pragma unroll
    for (int i = 0; i < 16; i++) { v[i] = __expf(v[i] - m); s += v[i]; }
    float inv = 1.0f / s;
#pragma unroll
    for (int i = 0; i < 16; i++) v[i] *= inv;

    //  0:0  1:p  2:a1-p  3:a1  4:a2-p  5:a2  6:a1+a2-2p  7:a1+a2-p
    //  8:1-(a1+a2-p)  9:1-(a1+a2-2p)  10:1-a2  11:1-a2+p
    // 12:1-a1  13:1-a1+p  14:1-p  15:1
    float A = v[8]+v[9]+v[10]+v[11]+v[12]+v[13]+v[14]+v[15];
    float B = (v[2]+v[3]+v[6]+v[7]) - (v[8]+v[9]+v[12]+v[13]);
    float C = (v[4]+v[5]+v[6]+v[7]) - (v[8]+v[9]+v[10]+v[11]);
    float D = v[1]-v[2]-v[4]-2.0f*v[6]-v[7]+v[8]+2.0f*v[9]+v[11]+v[13]-v[14];

    g_coeff[n] = make_float4(A, B, C, D);
}

// ---------------------------------------------------------------------------
// Persistent main kernel. grid=148, 1 block/SM, 3 x 64KB TMA ring buffers.
// Prefetch for pair k+2 is issued at the TOP of iteration k: buffer (k+2)%3
// was last read during iteration k-1 and the end-of-(k-1) __syncthreads
// guarantees all reads are done before any thread reaches the top of k.
// So during compute of pair k, TMAs for k+1 AND k+2 are in flight (depth 2).
// idx+coeff are register-resident for the whole kernel.
// ---------------------------------------------------------------------------
__global__ __launch_bounds__(THREADS, 1) void logic_kernel(
    const float* __restrict__ x,
    const int*   __restrict__ idx,
    float* __restrict__ out)
{
    extern __shared__ __align__(128) char smem[];
    const uint32_t buf_s = smem_u32(smem);
    const uint32_t fm0   = buf_s + NBUF * PAIR_BYTES;   // 3 full barriers

    const int tid = threadIdx.x;
    const int bid = blockIdx.x;

    // --- Preload idx (packed u16 pairs) + coefficients into registers ---
    uint32_t pidx[NPT];
    float4   cf[NPT];
    const int4* idx4 = reinterpret_cast<const int4*>(idx);  // 2 neurons per int4
#pragma unroll
    for (int g = 0; g < 4; g++) {
        int nbase = g * 2048 + tid * 4;            // 4 consecutive neurons
        int4 ia = __ldg(&idx4[nbase / 2]);         // neurons nbase, nbase+1
        int4 ib = __ldg(&idx4[nbase / 2 + 1]);     // neurons nbase+2, nbase+3
        pidx[g * 4 + 0] = (uint32_t)ia.x | ((uint32_t)ia.y << 16);
        pidx[g * 4 + 1] = (uint32_t)ia.z | ((uint32_t)ia.w << 16);
        pidx[g * 4 + 2] = (uint32_t)ib.x | ((uint32_t)ib.y << 16);
        pidx[g * 4 + 3] = (uint32_t)ib.z | ((uint32_t)ib.w << 16);
#pragma unroll
        for (int u = 0; u < 4; u++) cf[g * 4 + u] = g_coeff[nbase + u];
    }

    if (tid == 0) {
#pragma unroll
        for (int b = 0; b < NBUF; b++) mbar_init(fm0 + b * 8, 1);
    }
    __syncthreads();

    const int npairs = (PAIRS - bid + GRID - 1) / GRID;   // 6 or 7

    // --- Prologue: issue first two TMA loads (buffers 0,1) ---
    if (tid == 0) {
#pragma unroll
        for (int b = 0; b < 2; b++) {
            if (b < npairs) {
                mbar_expect_tx(fm0 + b * 8, PAIR_BYTES);
                tma_bulk_g2s(buf_s + b * PAIR_BYTES,
                             x + (size_t)(bid + b * GRID) * 2 * INPUT_SIZE,
                             PAIR_BYTES, fm0 + b * 8);
            }
        }
    }

    uint32_t fphase = 0;   // bit b = wait parity of full barrier b

    for (int k = 0; k < npairs; k++) {
        const int b = k % NBUF;

        // Prefetch pair k+2 into buffer (k+2)%NBUF. Safe: that buffer's
        // readers all passed the __syncthreads at the end of iteration k-1.
        if (tid == 0 && k + 2 < npairs) {
            const int pb = (k + 2) % NBUF;
            mbar_expect_tx(fm0 + pb * 8, PAIR_BYTES);
            tma_bulk_g2s(buf_s + pb * PAIR_BYTES,
                         x + (size_t)(bid + (k + 2) * GRID) * 2 * INPUT_SIZE,
                         PAIR_BYTES, fm0 + pb * 8);
        }

        mbar_wait(fm0 + b * 8, (fphase >> b) & 1u);
        fphase ^= (1u << b);

        const float* xs0 = reinterpret_cast<const float*>(smem) + b * (2 * INPUT_SIZE);
        const float* xs1 = xs0 + INPUT_SIZE;

        const int p = bid + k * GRID;
        float4* o0 = reinterpret_cast<float4*>(out + (size_t)(2 * p)     * NUM_NEURONS);
        float4* o1 = reinterpret_cast<float4*>(out + (size_t)(2 * p + 1) * NUM_NEURONS);

#pragma unroll
        for (int g = 0; g < 4; g++) {
            float4 r0, r1;
            float* q0 = reinterpret_cast<float*>(&r0);
            float* q1 = reinterpret_cast<float*>(&r1);
#pragma unroll
            for (int u = 0; u < 4; u++) {
                const uint32_t pk = pidx[g * 4 + u];
                const int i1 = pk & 0xFFFFu;
                const int i2 = pk >> 16;
                const float a10 = xs0[i1], a20 = xs0[i2];
                const float a11 = xs1[i1], a21 = xs1[i2];
                const float4 c = cf[g * 4 + u];
                q0[u] = fmaf(a10, fmaf(a20, c.w, c.y), fmaf(a20, c.z, c.x));
                q1[u] = fmaf(a11, fmaf(a21, c.w, c.y), fmaf(a21, c.z, c.x));
            }
            const int o = g * THREADS + tid;   // coalesced float4 stores
            o0[o] = r0;
            o1[o] = r1;
        }

        __syncthreads();   // everyone done reading buffer b
    }
}

extern "C" void kernel_launch(void* const* d_in, const int* in_sizes, int n_in,
                              void* d_out, int out_size) {
    const float* x    = (const float*)d_in[0];   // [2048, 8192] f32
    const float* w    = (const float*)d_in[1];   // [8192, 16]   f32
    const int*   conn = (const int*)d_in[2];     // [8192, 2]    i32
    float* out = (float*)d_out;                  // [2048, 8192] f32

    const int smem = NBUF * PAIR_BYTES + NBUF * 8;   // 192 KB + barriers
    cudaFuncSetAttribute(logic_kernel,
                         cudaFuncAttributeMaxDynamicSharedMemorySize, smem);

    coeff_kernel<<<NUM_NEURONS / 256, 256>>>(w);
    logic_kernel<<<GRID, THREADS, smem>>>(x, conn, out);
}